// round 8
// baseline (speedup 1.0000x reference)
#include <cuda_runtime.h>

#define NB 256
#define NT 1024
#define NI 64
#define NH 25
#define NG 100   // 4*H
#define NO 64
#define NM (NB*NT)  // 262144 rows
#define GROWS 150   // gates tile rows

// Precomputed input gates, layout [row][k][4] = (i_k, f_k, g_k, o_k): ~105 MB
static __device__ float g_gates[(size_t)NM * NG];
// Hidden states from the scan: g_hs[(b*NT + t)*NH + k] (~26 MB)
static __device__ float g_hs[(size_t)NM * NH];

typedef unsigned long long ull;

__device__ __forceinline__ ull pack2(float a, float b){
    ull r; asm("mov.b64 %0,{%1,%2};" : "=l"(r) : "f"(a), "f"(b)); return r;
}
__device__ __forceinline__ float2 unpack2(ull v){
    float2 r; asm("mov.b64 {%0,%1},%2;" : "=f"(r.x), "=f"(r.y) : "l"(v)); return r;
}
__device__ __forceinline__ ull fma2(ull a, ull b, ull c){
    ull d; asm("fma.rn.f32x2 %0,%1,%2,%3;" : "=l"(d) : "l"(a), "l"(b), "l"(c)); return d;
}
__device__ __forceinline__ ull add2(ull a, ull b){
    ull d; asm("add.rn.f32x2 %0,%1,%2;" : "=l"(d) : "l"(a), "l"(b)); return d;
}
__device__ __forceinline__ float tanha(float x){
    float r; asm("tanh.approx.f32 %0,%1;" : "=f"(r) : "f"(x)); return r;
}
__device__ __forceinline__ float sig_t(float x){
    return fmaf(tanha(0.5f * x), 0.5f, 0.5f);
}
__device__ __forceinline__ unsigned smem_u32(const void* p){
    unsigned a;
    asm("{ .reg .u64 t; cvta.to.shared.u64 t, %1; cvt.u32.u64 %0, t; }"
        : "=r"(a) : "l"(p));
    return a;
}

// ---------------------------------------------------------------------------
// Kernel 1: g_gates[row][k*4+{0..3}] = (i,f,g,o)_k pre-acts (unchanged R7).
// ---------------------------------------------------------------------------
__global__ void __launch_bounds__(256) gates_kernel(
    const float* __restrict__ x, const float* __restrict__ W_ih,
    const float* __restrict__ b_ih, const float* __restrict__ b_hh)
{
    __shared__ float xs[GROWS][34];
    __shared__ ull   wps[32][50];
    __shared__ float bsum[NG];

    const int tid   = threadIdx.x;          // 0..249
    const int pairc = tid % 10;
    const int rowt  = tid / 10;             // 0..24
    const int rowbase = blockIdx.x * GROWS;

    ull acc[6][5];
    #pragma unroll
    for (int r = 0; r < 6; r++)
        #pragma unroll
        for (int c = 0; c < 5; c++) acc[r][c] = 0ull;

    for (int pass = 0; pass < 2; pass++){
        const int ks = pass * 32;
        for (int idx = tid; idx < GROWS*32; idx += 250){
            int r = idx >> 5, k = idx & 31;
            int grow = rowbase + r;
            xs[r][k] = (grow < NM) ? x[(size_t)grow * NI + ks + k] : 0.0f;
        }
        for (int idx = tid; idx < 32*50; idx += 250){
            int k = idx / 50, c = idx % 50;
            int r0 = (c < 25) ? c      : 25 + c;
            int r1 = (c < 25) ? 25 + c : 50 + c;
            wps[k][c] = pack2(W_ih[r0 * NI + ks + k], W_ih[r1 * NI + ks + k]);
        }
        if (pass == 0)
            for (int j = tid; j < NG; j += 250) bsum[j] = b_ih[j] + b_hh[j];
        __syncthreads();

        #pragma unroll
        for (int kk = 0; kk < 16; kk++){
            float2 xv[6];
            ull    wv0[5], wv1[5];
            #pragma unroll
            for (int r = 0; r < 6; r++)
                xv[r] = *reinterpret_cast<const float2*>(&xs[rowt + 25*r][2*kk]);
            #pragma unroll
            for (int c = 0; c < 5; c++){
                wv0[c] = wps[2*kk    ][pairc + 10*c];
                wv1[c] = wps[2*kk + 1][pairc + 10*c];
            }
            ull xd0[6], xd1[6];
            #pragma unroll
            for (int r = 0; r < 6; r++){
                xd0[r] = pack2(xv[r].x, xv[r].x);
                xd1[r] = pack2(xv[r].y, xv[r].y);
            }
            #pragma unroll
            for (int r = 0; r < 6; r++)
                #pragma unroll
                for (int c = 0; c < 5; c++){
                    acc[r][c] = fma2(xd0[r], wv0[c], acc[r][c]);
                    acc[r][c] = fma2(xd1[r], wv1[c], acc[r][c]);
                }
        }
        __syncthreads();
    }

    #pragma unroll
    for (int r = 0; r < 6; r++){
        int grow = rowbase + rowt + 25*r;
        if (grow >= NM) continue;
        float* gp = g_gates + (size_t)grow * NG;
        #pragma unroll
        for (int cc = 0; cc < 5; cc++){
            int c = pairc + 10*cc;
            int base, r0, r1;
            if (c < 25){ base = 4*c;          r0 = c;      r1 = 25 + c; }
            else       { base = 4*(c-25) + 2; r0 = 25 + c; r1 = 50 + c; }
            float2 v = unpack2(acc[r][cc]);
            v.x += bsum[r0];
            v.y += bsum[r1];
            *reinterpret_cast<float2*>(gp + base) = v;
        }
    }
}

// ---------------------------------------------------------------------------
// Kernel 2: warp-private LSTM scan, GATES ONLY (50 FMA2/step — FC moved out
// to cut the rt=3 register-bank-bound FMA2 stream by a third).
// Stores h each step to g_hs (STG.32, off critical path).
// cp.async smem ring for gx: 16 slots x 16B/lane, distance 12.
// ---------------------------------------------------------------------------
#define RD   16
#define RPD  12

__global__ void __launch_bounds__(64, 1) lstm_kernel(
    const float* __restrict__ W_hh)
{
    __shared__ ull ring[2][RD][32][2];

    const int lane = threadIdx.x & 31;
    const int wrp  = threadIdx.x >> 5;
    const int b    = blockIdx.x * 2 + wrp;
    const int k    = (lane < NH) ? lane : NH - 1;

    const float* gx = g_gates + (size_t)b * NT * NG + 4 * k;
    float*       hp = g_hs    + (size_t)b * NT * NH + k;

    ull w_if[NH], w_go[NH];
    #pragma unroll
    for (int kk = 0; kk < NH; kk++){
        w_if[kk] = pack2(__ldg(W_hh + (     k) * NH + kk), __ldg(W_hh + (NH  + k) * NH + kk));
        w_go[kk] = pack2(__ldg(W_hh + (2*NH+k) * NH + kk), __ldg(W_hh + (3*NH+k) * NH + kk));
    }

    const unsigned rbase = smem_u32(&ring[wrp][0][lane][0]);
    #define SLOT_ADDR(s) (rbase + (unsigned)(s) * (32u * 16u))

    #pragma unroll
    for (int d = 0; d < RPD; d++){
        asm volatile("cp.async.ca.shared.global [%0], [%1], 16;"
                     :: "r"(SLOT_ADDR(d)), "l"(gx + (size_t)d * NG) : "memory");
        asm volatile("cp.async.commit_group;" ::: "memory");
    }

    float h = 0.0f, c = 0.0f;

    for (int tb = 0; tb < NT; tb += 4){
        #pragma unroll
        for (int u = 0; u < 4; u++){
            const int t = tb + u;
            asm volatile("cp.async.wait_group 11;" ::: "memory");
            float4 pv = *reinterpret_cast<const float4*>(
                            &ring[wrp][t & (RD-1)][lane][0]);

            {   // refill slot t+RPD
                unsigned pred = (t + RPD < NT) ? 1u : 0u;
                asm volatile(
                    "{ .reg .pred q; setp.ne.u32 q, %0, 0;"
                    "  @q cp.async.ca.shared.global [%1], [%2], 16; }"
                    :: "r"(pred), "r"(SLOT_ADDR((t + RPD) & (RD-1))),
                       "l"(gx + (size_t)(t + RPD) * NG) : "memory");
                asm volatile("cp.async.commit_group;" ::: "memory");
            }

            ull aif[4], ago[4];
            aif[0] = pack2(pv.x, pv.y); aif[1] = 0ull; aif[2] = 0ull; aif[3] = 0ull;
            ago[0] = pack2(pv.z, pv.w); ago[1] = 0ull; ago[2] = 0ull; ago[3] = 0ull;

            #pragma unroll
            for (int kk = 0; kk < NH; kk++){
                float hv = __shfl_sync(0xffffffffu, h, kk);
                ull hd = pack2(hv, hv);
                aif[kk & 3] = fma2(hd, w_if[kk], aif[kk & 3]);
                ago[kk & 3] = fma2(hd, w_go[kk], ago[kk & 3]);
            }

            float2 gif = unpack2(add2(add2(aif[0], aif[1]), add2(aif[2], aif[3])));
            float2 ggo = unpack2(add2(add2(ago[0], ago[1]), add2(ago[2], ago[3])));
            float iv = sig_t(gif.x);
            float fv = sig_t(gif.y);
            float gv = tanha(ggo.x);
            float ov = sig_t(ggo.y);
            c = fv * c + iv * gv;
            h = ov * tanha(c);

            if (lane < NH)
                hp[(size_t)t * NH] = h;     // off critical path
        }
    }
    #undef SLOT_ADDR
}

// ---------------------------------------------------------------------------
// Kernel 3: FC head GEMM: out[row] = h[row] @ W_fc^T + b_fc.
// M = 262144, K = 25, N = 64 (32 f32x2 pairs). Block: 128 rows, 256 threads;
// thread = 4 rows x 4 pairs (16 ull accums). rt3 FMA2 floor ~17 us chip-wide.
// ---------------------------------------------------------------------------
__global__ void __launch_bounds__(256) fc_kernel(
    const float* __restrict__ W_fc, const float* __restrict__ b_fc,
    float* __restrict__ out)
{
    __shared__ float hsm[128][27];   // stride 27 -> rows spread banks
    __shared__ ull   wsd[NH][32];    // packed (W[2j],W[2j+1]) per k
    __shared__ ull   bsd[32];

    const int tid = threadIdx.x;
    const size_t rowbase = (size_t)blockIdx.x * 128;

    {   // stage h tile: 128 rows x 25, vector-ish strided copy
        const float* src = g_hs + rowbase * NH;
        for (int idx = tid; idx < 128 * NH; idx += 256)
            hsm[idx / NH][idx % NH] = src[idx];
    }
    for (int idx = tid; idx < NH * 32; idx += 256){
        int kk = idx >> 5, j = idx & 31;
        wsd[kk][j] = pack2(W_fc[(2*j) * NH + kk], W_fc[(2*j+1) * NH + kk]);
    }
    if (tid < 32)
        bsd[tid] = pack2(b_fc[2*tid], b_fc[2*tid + 1]);
    __syncthreads();

    const int rc = tid >> 3;        // 0..31 -> rows 4*rc..4*rc+3
    const int jc = tid & 7;         // pairs jc, jc+8, jc+16, jc+24
    const int r0 = 4 * rc;

    ull acc[4][4];
    #pragma unroll
    for (int r = 0; r < 4; r++)
        #pragma unroll
        for (int p = 0; p < 4; p++) acc[r][p] = bsd[jc + 8*p];

    #pragma unroll
    for (int kk = 0; kk < NH; kk++){
        ull hv[4], wv[4];
        #pragma unroll
        for (int r = 0; r < 4; r++){
            float v = hsm[r0 + r][kk];
            hv[r] = pack2(v, v);
        }
        #pragma unroll
        for (int p = 0; p < 4; p++) wv[p] = wsd[kk][jc + 8*p];
        #pragma unroll
        for (int r = 0; r < 4; r++)
            #pragma unroll
            for (int p = 0; p < 4; p++)
                acc[r][p] = fma2(hv[r], wv[p], acc[r][p]);
    }

    #pragma unroll
    for (int r = 0; r < 4; r++){
        float* ob = out + (rowbase + r0 + r) * NO;
        #pragma unroll
        for (int p = 0; p < 4; p++)
            *reinterpret_cast<float2*>(ob + 2*(jc + 8*p)) = unpack2(acc[r][p]);
    }
}

extern "C" void kernel_launch(void* const* d_in, const int* in_sizes, int n_in,
                              void* d_out, int out_size)
{
    (void)in_sizes; (void)n_in; (void)out_size;
    const float* x    = (const float*)d_in[0];
    const float* W_ih = (const float*)d_in[1];
    const float* W_hh = (const float*)d_in[2];
    const float* b_ih = (const float*)d_in[3];
    const float* b_hh = (const float*)d_in[4];
    const float* W_fc = (const float*)d_in[5];
    const float* b_fc = (const float*)d_in[6];
    float* out = (float*)d_out;

    gates_kernel<<<(NM + GROWS - 1) / GROWS, 250>>>(x, W_ih, b_ih, b_hh);
    lstm_kernel<<<NB / 2, 64>>>(W_hh);
    fc_kernel<<<NM / 128, 256>>>(W_fc, b_fc, out);
}

// round 9
// speedup vs baseline: 1.0012x; 1.0012x over previous
#include <cuda_runtime.h>

#define NB 256
#define NT 1024
#define NI 64
#define NH 25
#define NG 100    // 4*H real gate columns
#define NGP 104   // padded gate stride (13*8; 416B rows -> 32B-aligned chunks)
#define NO 64
#define NM (NB*NT)  // 262144 rows

// Precomputed input gates, layout [row][k*4+{i,f,g,o}] padded to 104: ~109 MB
static __device__ float g_gates[(size_t)NM * NGP];

typedef unsigned long long ull;
typedef unsigned int uint;

__device__ __forceinline__ ull pack2(float a, float b){
    ull r; asm("mov.b64 %0,{%1,%2};" : "=l"(r) : "f"(a), "f"(b)); return r;
}
__device__ __forceinline__ float2 unpack2(ull v){
    float2 r; asm("mov.b64 {%0,%1},%2;" : "=f"(r.x), "=f"(r.y) : "l"(v)); return r;
}
__device__ __forceinline__ ull fma2(ull a, ull b, ull c){
    ull d; asm("fma.rn.f32x2 %0,%1,%2,%3;" : "=l"(d) : "l"(a), "l"(b), "l"(c)); return d;
}
__device__ __forceinline__ ull add2(ull a, ull b){
    ull d; asm("add.rn.f32x2 %0,%1,%2;" : "=l"(d) : "l"(a), "l"(b)); return d;
}
__device__ __forceinline__ float tanha(float x){
    float r; asm("tanh.approx.f32 %0,%1;" : "=f"(r) : "f"(x)); return r;
}
__device__ __forceinline__ float sig_t(float x){
    return fmaf(tanha(0.5f * x), 0.5f, 0.5f);
}
__device__ __forceinline__ unsigned smem_u32(const void* p){
    unsigned a;
    asm("{ .reg .u64 t; cvta.to.shared.u64 t, %1; cvt.u32.u64 %0, t; }"
        : "=r"(a) : "l"(p));
    return a;
}
__device__ __forceinline__ uint to_tf32(float v){
    uint r; asm("cvt.rna.tf32.f32 %0,%1;" : "=r"(r) : "f"(v)); return r;
}

#define MMA_TF32(c, a0,a1,a2,a3, b0,b1)                                   \
    asm volatile("mma.sync.aligned.m16n8k8.row.col.f32.tf32.tf32.f32 "    \
        "{%0,%1,%2,%3}, {%4,%5,%6,%7}, {%8,%9}, {%0,%1,%2,%3};"           \
        : "+f"((c)[0]), "+f"((c)[1]), "+f"((c)[2]), "+f"((c)[3])          \
        : "r"(a0), "r"(a1), "r"(a2), "r"(a3), "r"(b0), "r"(b1))

// ---------------------------------------------------------------------------
// Kernel 1: gates via 3xTF32 tensor-core GEMM.
// out[row][n] = x[row] . W_ih[perm(n)] + bias[perm(n)], perm(n=4k+q)=q*25+k,
// so results land directly in the scan's (i,f,g,o)_k interleaved layout.
// Split x=hi+lo, W=hi+lo (tf32 rna); acc += ah*bh + al*bh + ah*bl  (~fp32).
// Block: 64 rows x 104 cols, 128 threads (4 warps x 16 rows); K in 2 passes.
// ---------------------------------------------------------------------------
__global__ void __launch_bounds__(128) gates_kernel(
    const float* __restrict__ x, const float* __restrict__ W_ih,
    const float* __restrict__ b_ih, const float* __restrict__ b_hh)
{
    __shared__ uint  xs_hi[64][36], xs_lo[64][36];   // stride 36: bank (4r+c)%32
    __shared__ uint  bs_hi[32][NGP], bs_lo[32][NGP]; // stride 104: bank (8k+n)%32
    __shared__ float bsum[NGP];

    const int tid  = threadIdx.x;
    const int lane = tid & 31;
    const int wid  = tid >> 5;          // 0..3
    const int grp  = lane >> 2;         // 0..7
    const int qid  = lane & 3;          // 0..3
    const int rowbase = blockIdx.x * 64;

    float acc[13][4];
    #pragma unroll
    for (int nt = 0; nt < 13; nt++)
        #pragma unroll
        for (int i = 0; i < 4; i++) acc[nt][i] = 0.0f;

    // permuted bias
    for (int n = tid; n < NGP; n += 128){
        int q = n & 3, kk = n >> 2;
        bsum[n] = (kk < NH) ? (b_ih[q*NH + kk] + b_hh[q*NH + kk]) : 0.0f;
    }

    for (int pass = 0; pass < 2; pass++){
        const int ks = pass * 32;
        __syncthreads();   // pass>0: prior reads done before restaging

        for (int idx = tid; idx < 64*32; idx += 128){
            int r = idx >> 5, k = idx & 31;
            float v = x[(size_t)(rowbase + r) * NI + ks + k];
            uint hb = to_tf32(v);
            uint lb = to_tf32(v - __uint_as_float(hb));
            xs_hi[r][k] = hb;
            xs_lo[r][k] = lb;
        }
        for (int idx = tid; idx < 32*NGP; idx += 128){
            int k = idx / NGP, n = idx - k * NGP;
            int q = n & 3, kk = n >> 2;
            float v = (kk < NH) ? W_ih[(q*NH + kk) * NI + ks + k] : 0.0f;
            uint hb = to_tf32(v);
            uint lb = to_tf32(v - __uint_as_float(hb));
            bs_hi[k][n] = hb;
            bs_lo[k][n] = lb;
        }
        __syncthreads();

        #pragma unroll
        for (int kst = 0; kst < 4; kst++){
            const int r0 = wid * 16 + grp;
            const int c0 = kst * 8 + qid;
            uint ah0 = xs_hi[r0][c0],     ah1 = xs_hi[r0+8][c0];
            uint ah2 = xs_hi[r0][c0+4],   ah3 = xs_hi[r0+8][c0+4];
            uint al0 = xs_lo[r0][c0],     al1 = xs_lo[r0+8][c0];
            uint al2 = xs_lo[r0][c0+4],   al3 = xs_lo[r0+8][c0+4];
            const int bk = kst * 8 + qid;
            #pragma unroll
            for (int nt = 0; nt < 13; nt++){
                int bn = nt * 8 + grp;
                uint bh0 = bs_hi[bk][bn], bh1 = bs_hi[bk+4][bn];
                uint bl0 = bs_lo[bk][bn], bl1 = bs_lo[bk+4][bn];
                MMA_TF32(acc[nt], ah0, ah1, ah2, ah3, bh0, bh1);
                MMA_TF32(acc[nt], al0, al1, al2, al3, bh0, bh1);
                MMA_TF32(acc[nt], ah0, ah1, ah2, ah3, bl0, bl1);
            }
        }
    }

    // epilogue: bias + store (float2, 32B-aligned chunks per 4-lane group)
    const size_t rg = (size_t)(rowbase + wid * 16 + grp);
    #pragma unroll
    for (int nt = 0; nt < 13; nt++){
        int col = nt * 8 + 2 * qid;
        float2 bsv = *reinterpret_cast<const float2*>(&bsum[col]);
        float2 v0 = { acc[nt][0] + bsv.x, acc[nt][1] + bsv.y };
        float2 v1 = { acc[nt][2] + bsv.x, acc[nt][3] + bsv.y };
        *reinterpret_cast<float2*>(&g_gates[ rg      * NGP + col]) = v0;
        *reinterpret_cast<float2*>(&g_gates[(rg + 8) * NGP + col]) = v1;
    }
}

// ---------------------------------------------------------------------------
// Kernel 2: warp-private LSTM scan + fused FC (R7 structure, 158us proven).
// cp.async smem ring for gx (16 slots x 16B/lane, distance 12); 4-way trees.
// ---------------------------------------------------------------------------
#define RD   16
#define RPD  12

__global__ void __launch_bounds__(64, 1) lstm_kernel(
    const float* __restrict__ W_hh, const float* __restrict__ W_fc,
    const float* __restrict__ b_fc, float* __restrict__ out)
{
    __shared__ ull ring[2][RD][32][2];

    const int lane = threadIdx.x & 31;
    const int wrp  = threadIdx.x >> 5;
    const int b    = blockIdx.x * 2 + wrp;
    const int k    = (lane < NH) ? lane : NH - 1;
    const int o0   = 2 * lane;

    const float* gx = g_gates + (size_t)b * NT * NGP + 4 * k;
    float*       ob = out     + (size_t)b * NT * NO + o0;

    ull w_if[NH], w_go[NH], wf[NH];
    #pragma unroll
    for (int kk = 0; kk < NH; kk++){
        w_if[kk] = pack2(__ldg(W_hh + (     k) * NH + kk), __ldg(W_hh + (NH  + k) * NH + kk));
        w_go[kk] = pack2(__ldg(W_hh + (2*NH+k) * NH + kk), __ldg(W_hh + (3*NH+k) * NH + kk));
        wf[kk]   = pack2(__ldg(W_fc + o0 * NH + kk),       __ldg(W_fc + (o0+1) * NH + kk));
    }
    const ull bfc = pack2(__ldg(b_fc + o0), __ldg(b_fc + o0 + 1));

    const unsigned rbase = smem_u32(&ring[wrp][0][lane][0]);
    #define SLOT_ADDR(s) (rbase + (unsigned)(s) * (32u * 16u))

    #pragma unroll
    for (int d = 0; d < RPD; d++){
        asm volatile("cp.async.ca.shared.global [%0], [%1], 16;"
                     :: "r"(SLOT_ADDR(d)), "l"(gx + (size_t)d * NGP) : "memory");
        asm volatile("cp.async.commit_group;" ::: "memory");
    }

    float h = 0.0f, c = 0.0f;

    for (int tb = 0; tb < NT; tb += 4){
        #pragma unroll
        for (int u = 0; u < 4; u++){
            const int t = tb + u;
            asm volatile("cp.async.wait_group 11;" ::: "memory");
            float4 pv = *reinterpret_cast<const float4*>(
                            &ring[wrp][t & (RD-1)][lane][0]);

            {   // refill slot t+RPD
                unsigned pred = (t + RPD < NT) ? 1u : 0u;
                asm volatile(
                    "{ .reg .pred q; setp.ne.u32 q, %0, 0;"
                    "  @q cp.async.ca.shared.global [%1], [%2], 16; }"
                    :: "r"(pred), "r"(SLOT_ADDR((t + RPD) & (RD-1))),
                       "l"(gx + (size_t)(t + RPD) * NGP) : "memory");
                asm volatile("cp.async.commit_group;" ::: "memory");
            }

            ull aif[4], ago[4], afc[2];
            aif[0] = pack2(pv.x, pv.y); aif[1] = 0ull; aif[2] = 0ull; aif[3] = 0ull;
            ago[0] = pack2(pv.z, pv.w); ago[1] = 0ull; ago[2] = 0ull; ago[3] = 0ull;
            afc[0] = bfc;               afc[1] = 0ull;

            #pragma unroll
            for (int kk = 0; kk < NH; kk++){
                float hv = __shfl_sync(0xffffffffu, h, kk);
                ull hd = pack2(hv, hv);
                aif[kk & 3] = fma2(hd, w_if[kk], aif[kk & 3]);
                ago[kk & 3] = fma2(hd, w_go[kk], ago[kk & 3]);
                afc[kk & 1] = fma2(hd, wf[kk],   afc[kk & 1]);
            }
            if (t > 0)
                *reinterpret_cast<float2*>(ob + (size_t)(t - 1) * NO) =
                    unpack2(add2(afc[0], afc[1]));

            float2 gif = unpack2(add2(add2(aif[0], aif[1]), add2(aif[2], aif[3])));
            float2 ggo = unpack2(add2(add2(ago[0], ago[1]), add2(ago[2], ago[3])));
            float iv = sig_t(gif.x);
            float fv = sig_t(gif.y);
            float gv = tanha(ggo.x);
            float ov = sig_t(ggo.y);
            c = fv * c + iv * gv;
            h = ov * tanha(c);
        }
    }
    {
        ull a0 = bfc, a1 = 0ull;
        #pragma unroll
        for (int kk = 0; kk < NH; kk++){
            float hv = __shfl_sync(0xffffffffu, h, kk);
            ull hd = pack2(hv, hv);
            if (kk & 1) a1 = fma2(hd, wf[kk], a1);
            else        a0 = fma2(hd, wf[kk], a0);
        }
        *reinterpret_cast<float2*>(ob + (size_t)(NT - 1) * NO) = unpack2(add2(a0, a1));
    }
    #undef SLOT_ADDR
}

extern "C" void kernel_launch(void* const* d_in, const int* in_sizes, int n_in,
                              void* d_out, int out_size)
{
    (void)in_sizes; (void)n_in; (void)out_size;
    const float* x    = (const float*)d_in[0];
    const float* W_ih = (const float*)d_in[1];
    const float* W_hh = (const float*)d_in[2];
    const float* b_ih = (const float*)d_in[3];
    const float* b_hh = (const float*)d_in[4];
    const float* W_fc = (const float*)d_in[5];
    const float* b_fc = (const float*)d_in[6];
    float* out = (float*)d_out;

    gates_kernel<<<NM / 64, 128>>>(x, W_ih, b_ih, b_hh);
    lstm_kernel<<<NB / 2, 64>>>(W_hh, W_fc, b_fc, out);
}

// round 10
// speedup vs baseline: 1.4190x; 1.4173x over previous
#include <cuda_runtime.h>

#define NB 256
#define NT 1024
#define NI 64
#define NH 25
#define NG 100    // real gate columns
#define NGP 104   // padded gate stride (13*8)
#define NO 64
#define NM (NB*NT)  // 262144 rows

// Precomputed input gates, layout [row][k*4+{i,f,g,o}] padded to 104: ~109 MB
static __device__ float g_gates[(size_t)NM * NGP];
// Precomputed W_ih fragments: [kstg 0..7][n 0..103][qid 0..3] = {bh0,bh1,bl0,bl1}
static __device__ uint4 g_wq[8 * NGP * 4];
static __device__ float g_bsum[NGP];

typedef unsigned long long ull;
typedef unsigned int uint;

__device__ __forceinline__ ull pack2(float a, float b){
    ull r; asm("mov.b64 %0,{%1,%2};" : "=l"(r) : "f"(a), "f"(b)); return r;
}
__device__ __forceinline__ float2 unpack2(ull v){
    float2 r; asm("mov.b64 {%0,%1},%2;" : "=f"(r.x), "=f"(r.y) : "l"(v)); return r;
}
__device__ __forceinline__ ull fma2(ull a, ull b, ull c){
    ull d; asm("fma.rn.f32x2 %0,%1,%2,%3;" : "=l"(d) : "l"(a), "l"(b), "l"(c)); return d;
}
__device__ __forceinline__ ull add2(ull a, ull b){
    ull d; asm("add.rn.f32x2 %0,%1,%2;" : "=l"(d) : "l"(a), "l"(b)); return d;
}
__device__ __forceinline__ float tanha(float x){
    float r; asm("tanh.approx.f32 %0,%1;" : "=f"(r) : "f"(x)); return r;
}
__device__ __forceinline__ float sig_t(float x){
    return fmaf(tanha(0.5f * x), 0.5f, 0.5f);
}
__device__ __forceinline__ unsigned smem_u32(const void* p){
    unsigned a;
    asm("{ .reg .u64 t; cvta.to.shared.u64 t, %1; cvt.u32.u64 %0, t; }"
        : "=r"(a) : "l"(p));
    return a;
}
__device__ __forceinline__ uint to_tf32(float v){
    uint r; asm("cvt.rna.tf32.f32 %0,%1;" : "=r"(r) : "f"(v)); return r;
}

#define MMA_TF32(c, a0,a1,a2,a3, b0,b1)                                   \
    asm volatile("mma.sync.aligned.m16n8k8.row.col.f32.tf32.tf32.f32 "    \
        "{%0,%1,%2,%3}, {%4,%5,%6,%7}, {%8,%9}, {%0,%1,%2,%3};"           \
        : "+f"((c)[0]), "+f"((c)[1]), "+f"((c)[2]), "+f"((c)[3])          \
        : "r"(a0), "r"(a1), "r"(a2), "r"(a3), "r"(b0), "r"(b1))

// ---------------------------------------------------------------------------
// Kernel 0: precompute permuted + tf32-split + fragment-interleaved W, bias.
// perm(n=4k+q) = gate row q*25+k. k0 = kstg*8+qid, k1 = k0+4.
// ---------------------------------------------------------------------------
__global__ void prep_kernel(const float* __restrict__ W_ih,
                            const float* __restrict__ b_ih,
                            const float* __restrict__ b_hh)
{
    int tid = blockIdx.x * blockDim.x + threadIdx.x;
    const int total = 8 * NGP * 4;
    for (int i = tid; i < total; i += blockDim.x * gridDim.x){
        int qid  = i & 3;
        int n    = (i >> 2) % NGP;
        int kstg = i / (NGP * 4);
        int q = n & 3, kk = n >> 2;
        int k0 = kstg * 8 + qid, k1 = k0 + 4;
        float v0 = (kk < NH) ? W_ih[(q*NH + kk) * NI + k0] : 0.0f;
        float v1 = (kk < NH) ? W_ih[(q*NH + kk) * NI + k1] : 0.0f;
        uint h0 = to_tf32(v0), h1 = to_tf32(v1);
        uint l0 = to_tf32(v0 - __uint_as_float(h0));
        uint l1 = to_tf32(v1 - __uint_as_float(h1));
        g_wq[i] = make_uint4(h0, h1, l0, l1);
    }
    if (tid < NGP){
        int q = tid & 3, kk = tid >> 2;
        g_bsum[tid] = (kk < NH) ? (b_ih[q*NH + kk] + b_hh[q*NH + kk]) : 0.0f;
    }
}

// ---------------------------------------------------------------------------
// Kernel 1: gates via 3xTF32 tensor-core GEMM, staging-lean.
// B: linear cp.async of precomputed fragments; 1 LDS.128 per (kst,nt).
// x: float4 LDG + in-register hi/lo split.
// Block: 64 rows x 104 cols, 128 threads; K in 2 passes of 32.
// ---------------------------------------------------------------------------
__global__ void __launch_bounds__(128) gates_kernel(const float* __restrict__ x)
{
    __shared__ uint  xs_hi[64][36], xs_lo[64][36];   // bank (4r+c)%32: free
    __shared__ uint4 bq[4][NGP][4];                  // [kst][n][qid] fragments

    const int tid  = threadIdx.x;
    const int lane = tid & 31;
    const int wid  = tid >> 5;          // 0..3
    const int grp  = lane >> 2;         // 0..7
    const int qid  = lane & 3;          // 0..3
    const int rowbase = blockIdx.x * 64;

    float acc[13][4];
    #pragma unroll
    for (int nt = 0; nt < 13; nt++)
        #pragma unroll
        for (int i = 0; i < 4; i++) acc[nt][i] = 0.0f;

    const unsigned bq_s = smem_u32(&bq[0][0][0]);

    for (int pass = 0; pass < 2; pass++){
        const int ks = pass * 32;
        __syncthreads();   // prior-pass reads complete before restaging

        // B fragments: linear 26624B cp.async copy (13 chunks/thread)
        {
            const char* src = reinterpret_cast<const char*>(g_wq)
                              + (size_t)pass * 4 * NGP * 4 * 16;
            #pragma unroll
            for (int i = 0; i < 13; i++){
                int off = (tid + i * 128) * 16;
                asm volatile("cp.async.ca.shared.global [%0], [%1], 16;"
                             :: "r"(bq_s + off), "l"(src + off) : "memory");
            }
            asm volatile("cp.async.commit_group;" ::: "memory");
        }

        // x tile: 64 rows x 32 cols, float4 loads + hi/lo split
        #pragma unroll
        for (int i = 0; i < 4; i++){
            int idx = tid + i * 128;        // 0..511
            int r = idx >> 3, f4 = idx & 7;
            float4 v = *reinterpret_cast<const float4*>(
                x + (size_t)(rowbase + r) * NI + ks + f4 * 4);
            uint4 hb, lb;
            hb.x = to_tf32(v.x); lb.x = to_tf32(v.x - __uint_as_float(hb.x));
            hb.y = to_tf32(v.y); lb.y = to_tf32(v.y - __uint_as_float(hb.y));
            hb.z = to_tf32(v.z); lb.z = to_tf32(v.z - __uint_as_float(hb.z));
            hb.w = to_tf32(v.w); lb.w = to_tf32(v.w - __uint_as_float(hb.w));
            *reinterpret_cast<uint4*>(&xs_hi[r][f4 * 4]) = hb;
            *reinterpret_cast<uint4*>(&xs_lo[r][f4 * 4]) = lb;
        }
        asm volatile("cp.async.wait_group 0;" ::: "memory");
        __syncthreads();

        #pragma unroll
        for (int kst = 0; kst < 4; kst++){
            const int r0 = wid * 16 + grp;
            const int c0 = kst * 8 + qid;
            uint ah0 = xs_hi[r0][c0],   ah1 = xs_hi[r0+8][c0];
            uint ah2 = xs_hi[r0][c0+4], ah3 = xs_hi[r0+8][c0+4];
            uint al0 = xs_lo[r0][c0],   al1 = xs_lo[r0+8][c0];
            uint al2 = xs_lo[r0][c0+4], al3 = xs_lo[r0+8][c0+4];
            #pragma unroll
            for (int nt = 0; nt < 13; nt++){
                uint4 bv = bq[kst][nt * 8 + grp][qid];  // {bh0,bh1,bl0,bl1}
                MMA_TF32(acc[nt], ah0, ah1, ah2, ah3, bv.x, bv.y);
                MMA_TF32(acc[nt], al0, al1, al2, al3, bv.x, bv.y);
                MMA_TF32(acc[nt], ah0, ah1, ah2, ah3, bv.z, bv.w);
            }
        }
    }

    // epilogue: bias + store (float2, 32B-aligned per 4-lane group)
    const size_t rg = (size_t)(rowbase + wid * 16 + grp);
    #pragma unroll
    for (int nt = 0; nt < 13; nt++){
        int col = nt * 8 + 2 * qid;
        float2 bsv = *reinterpret_cast<const float2*>(&g_bsum[col]);
        float2 v0 = { acc[nt][0] + bsv.x, acc[nt][1] + bsv.y };
        float2 v1 = { acc[nt][2] + bsv.x, acc[nt][3] + bsv.y };
        *reinterpret_cast<float2*>(&g_gates[ rg      * NGP + col]) = v0;
        *reinterpret_cast<float2*>(&g_gates[(rg + 8) * NGP + col]) = v1;
    }
}

// ---------------------------------------------------------------------------
// Kernel 2: warp-private LSTM scan + fused FC (proven 158us, unchanged).
// ---------------------------------------------------------------------------
#define RD   16
#define RPD  12

__global__ void __launch_bounds__(64, 1) lstm_kernel(
    const float* __restrict__ W_hh, const float* __restrict__ W_fc,
    const float* __restrict__ b_fc, float* __restrict__ out)
{
    __shared__ ull ring[2][RD][32][2];

    const int lane = threadIdx.x & 31;
    const int wrp  = threadIdx.x >> 5;
    const int b    = blockIdx.x * 2 + wrp;
    const int k    = (lane < NH) ? lane : NH - 1;
    const int o0   = 2 * lane;

    const float* gx = g_gates + (size_t)b * NT * NGP + 4 * k;
    float*       ob = out     + (size_t)b * NT * NO + o0;

    ull w_if[NH], w_go[NH], wf[NH];
    #pragma unroll
    for (int kk = 0; kk < NH; kk++){
        w_if[kk] = pack2(__ldg(W_hh + (     k) * NH + kk), __ldg(W_hh + (NH  + k) * NH + kk));
        w_go[kk] = pack2(__ldg(W_hh + (2*NH+k) * NH + kk), __ldg(W_hh + (3*NH+k) * NH + kk));
        wf[kk]   = pack2(__ldg(W_fc + o0 * NH + kk),       __ldg(W_fc + (o0+1) * NH + kk));
    }
    const ull bfc = pack2(__ldg(b_fc + o0), __ldg(b_fc + o0 + 1));

    const unsigned rbase = smem_u32(&ring[wrp][0][lane][0]);
    #define SLOT_ADDR(s) (rbase + (unsigned)(s) * (32u * 16u))

    #pragma unroll
    for (int d = 0; d < RPD; d++){
        asm volatile("cp.async.ca.shared.global [%0], [%1], 16;"
                     :: "r"(SLOT_ADDR(d)), "l"(gx + (size_t)d * NGP) : "memory");
        asm volatile("cp.async.commit_group;" ::: "memory");
    }

    float h = 0.0f, c = 0.0f;

    for (int tb = 0; tb < NT; tb += 4){
        #pragma unroll
        for (int u = 0; u < 4; u++){
            const int t = tb + u;
            asm volatile("cp.async.wait_group 11;" ::: "memory");
            float4 pv = *reinterpret_cast<const float4*>(
                            &ring[wrp][t & (RD-1)][lane][0]);

            {   // refill slot t+RPD
                unsigned pred = (t + RPD < NT) ? 1u : 0u;
                asm volatile(
                    "{ .reg .pred q; setp.ne.u32 q, %0, 0;"
                    "  @q cp.async.ca.shared.global [%1], [%2], 16; }"
                    :: "r"(pred), "r"(SLOT_ADDR((t + RPD) & (RD-1))),
                       "l"(gx + (size_t)(t + RPD) * NGP) : "memory");
                asm volatile("cp.async.commit_group;" ::: "memory");
            }

            ull aif[4], ago[4], afc[2];
            aif[0] = pack2(pv.x, pv.y); aif[1] = 0ull; aif[2] = 0ull; aif[3] = 0ull;
            ago[0] = pack2(pv.z, pv.w); ago[1] = 0ull; ago[2] = 0ull; ago[3] = 0ull;
            afc[0] = bfc;               afc[1] = 0ull;

            #pragma unroll
            for (int kk = 0; kk < NH; kk++){
                float hv = __shfl_sync(0xffffffffu, h, kk);
                ull hd = pack2(hv, hv);
                aif[kk & 3] = fma2(hd, w_if[kk], aif[kk & 3]);
                ago[kk & 3] = fma2(hd, w_go[kk], ago[kk & 3]);
                afc[kk & 1] = fma2(hd, wf[kk],   afc[kk & 1]);
            }
            if (t > 0)
                *reinterpret_cast<float2*>(ob + (size_t)(t - 1) * NO) =
                    unpack2(add2(afc[0], afc[1]));

            float2 gif = unpack2(add2(add2(aif[0], aif[1]), add2(aif[2], aif[3])));
            float2 ggo = unpack2(add2(add2(ago[0], ago[1]), add2(ago[2], ago[3])));
            float iv = sig_t(gif.x);
            float fv = sig_t(gif.y);
            float gv = tanha(ggo.x);
            float ov = sig_t(ggo.y);
            c = fv * c + iv * gv;
            h = ov * tanha(c);
        }
    }
    {
        ull a0 = bfc, a1 = 0ull;
        #pragma unroll
        for (int kk = 0; kk < NH; kk++){
            float hv = __shfl_sync(0xffffffffu, h, kk);
            ull hd = pack2(hv, hv);
            if (kk & 1) a1 = fma2(hd, wf[kk], a1);
            else        a0 = fma2(hd, wf[kk], a0);
        }
        *reinterpret_cast<float2*>(ob + (size_t)(NT - 1) * NO) = unpack2(add2(a0, a1));
    }
    #undef SLOT_ADDR
}

extern "C" void kernel_launch(void* const* d_in, const int* in_sizes, int n_in,
                              void* d_out, int out_size)
{
    (void)in_sizes; (void)n_in; (void)out_size;
    const float* x    = (const float*)d_in[0];
    const float* W_ih = (const float*)d_in[1];
    const float* W_hh = (const float*)d_in[2];
    const float* b_ih = (const float*)d_in[3];
    const float* b_hh = (const float*)d_in[4];
    const float* W_fc = (const float*)d_in[5];
    const float* b_fc = (const float*)d_in[6];
    float* out = (float*)d_out;

    prep_kernel<<<8, 256>>>(W_ih, b_ih, b_hh);
    gates_kernel<<<NM / 64, 128>>>(x);
    lstm_kernel<<<NB / 2, 64>>>(W_hh, W_fc, b_fc, out);
}

// round 12
// speedup vs baseline: 1.4400x; 1.0147x over previous
#include <cuda_runtime.h>

#define NB 256
#define NT 1024
#define NI 64
#define NH 25
#define NG 100    // real gate columns
#define NGP 104   // padded gate stride (13*8)
#define NO 64
#define NM (NB*NT)  // 262144 rows

// Precomputed input gates, layout [row][k*4+{i,f,g,o}] padded to 104: ~109 MB
static __device__ float g_gates[(size_t)NM * NGP];
// Precomputed W_ih fragments: [kstg 0..7][n 0..103][qid 0..3] = {bh0,bh1,bl0,bl1}
static __device__ uint4 g_wq[8 * NGP * 4];
static __device__ float g_bsum[NGP];

typedef unsigned long long ull;
typedef unsigned int uint;

__device__ __forceinline__ ull pack2(float a, float b){
    ull r; asm("mov.b64 %0,{%1,%2};" : "=l"(r) : "f"(a), "f"(b)); return r;
}
__device__ __forceinline__ float2 unpack2(ull v){
    float2 r; asm("mov.b64 {%0,%1},%2;" : "=f"(r.x), "=f"(r.y) : "l"(v)); return r;
}
__device__ __forceinline__ ull fma2(ull a, ull b, ull c){
    ull d; asm("fma.rn.f32x2 %0,%1,%2,%3;" : "=l"(d) : "l"(a), "l"(b), "l"(c)); return d;
}
__device__ __forceinline__ ull add2(ull a, ull b){
    ull d; asm("add.rn.f32x2 %0,%1,%2;" : "=l"(d) : "l"(a), "l"(b)); return d;
}
__device__ __forceinline__ float tanha(float x){
    float r; asm("tanh.approx.f32 %0,%1;" : "=f"(r) : "f"(x)); return r;
}
__device__ __forceinline__ float sig_t(float x){
    return fmaf(tanha(0.5f * x), 0.5f, 0.5f);
}
__device__ __forceinline__ unsigned smem_u32(const void* p){
    unsigned a;
    asm("{ .reg .u64 t; cvta.to.shared.u64 t, %1; cvt.u32.u64 %0, t; }"
        : "=r"(a) : "l"(p));
    return a;
}
__device__ __forceinline__ uint to_tf32(float v){
    uint r; asm("cvt.rna.tf32.f32 %0,%1;" : "=r"(r) : "f"(v)); return r;
}

#define MMA_TF32(c, a0,a1,a2,a3, b0,b1)                                   \
    asm volatile("mma.sync.aligned.m16n8k8.row.col.f32.tf32.tf32.f32 "    \
        "{%0,%1,%2,%3}, {%4,%5,%6,%7}, {%8,%9}, {%0,%1,%2,%3};"           \
        : "+f"((c)[0]), "+f"((c)[1]), "+f"((c)[2]), "+f"((c)[3])          \
        : "r"(a0), "r"(a1), "r"(a2), "r"(a3), "r"(b0), "r"(b1))

// ---------------------------------------------------------------------------
// Kernel 0: precompute permuted + tf32-split + fragment-interleaved W, bias.
// ---------------------------------------------------------------------------
__global__ void prep_kernel(const float* __restrict__ W_ih,
                            const float* __restrict__ b_ih,
                            const float* __restrict__ b_hh)
{
    int tid = blockIdx.x * blockDim.x + threadIdx.x;
    const int total = 8 * NGP * 4;
    for (int i = tid; i < total; i += blockDim.x * gridDim.x){
        int qid  = i & 3;
        int n    = (i >> 2) % NGP;
        int kstg = i / (NGP * 4);
        int q = n & 3, kk = n >> 2;
        int k0 = kstg * 8 + qid, k1 = k0 + 4;
        float v0 = (kk < NH) ? W_ih[(q*NH + kk) * NI + k0] : 0.0f;
        float v1 = (kk < NH) ? W_ih[(q*NH + kk) * NI + k1] : 0.0f;
        uint h0 = to_tf32(v0), h1 = to_tf32(v1);
        uint l0 = to_tf32(v0 - __uint_as_float(h0));
        uint l1 = to_tf32(v1 - __uint_as_float(h1));
        g_wq[i] = make_uint4(h0, h1, l0, l1);
    }
    if (tid < NGP){
        int q = tid & 3, kk = tid >> 2;
        g_bsum[tid] = (kk < NH) ? (b_ih[q*NH + kk] + b_hh[q*NH + kk]) : 0.0f;
    }
}

// ---------------------------------------------------------------------------
// Kernel 1: gates via 3xTF32 tensor-core GEMM (R10 staging-lean, unchanged).
// ---------------------------------------------------------------------------
__global__ void __launch_bounds__(128) gates_kernel(const float* __restrict__ x)
{
    __shared__ uint  xs_hi[64][36], xs_lo[64][36];
    __shared__ uint4 bq[4][NGP][4];

    const int tid  = threadIdx.x;
    const int lane = tid & 31;
    const int wid  = tid >> 5;
    const int grp  = lane >> 2;
    const int qid  = lane & 3;
    const int rowbase = blockIdx.x * 64;

    float acc[13][4];
    #pragma unroll
    for (int nt = 0; nt < 13; nt++)
        #pragma unroll
        for (int i = 0; i < 4; i++) acc[nt][i] = 0.0f;

    const unsigned bq_s = smem_u32(&bq[0][0][0]);

    for (int pass = 0; pass < 2; pass++){
        const int ks = pass * 32;
        __syncthreads();

        {
            const char* src = reinterpret_cast<const char*>(g_wq)
                              + (size_t)pass * 4 * NGP * 4 * 16;
            #pragma unroll
            for (int i = 0; i < 13; i++){
                int off = (tid + i * 128) * 16;
                asm volatile("cp.async.ca.shared.global [%0], [%1], 16;"
                             :: "r"(bq_s + off), "l"(src + off) : "memory");
            }
            asm volatile("cp.async.commit_group;" ::: "memory");
        }

        #pragma unroll
        for (int i = 0; i < 4; i++){
            int idx = tid + i * 128;
            int r = idx >> 3, f4 = idx & 7;
            float4 v = *reinterpret_cast<const float4*>(
                x + (size_t)(rowbase + r) * NI + ks + f4 * 4);
            uint4 hb, lb;
            hb.x = to_tf32(v.x); lb.x = to_tf32(v.x - __uint_as_float(hb.x));
            hb.y = to_tf32(v.y); lb.y = to_tf32(v.y - __uint_as_float(hb.y));
            hb.z = to_tf32(v.z); lb.z = to_tf32(v.z - __uint_as_float(hb.z));
            hb.w = to_tf32(v.w); lb.w = to_tf32(v.w - __uint_as_float(hb.w));
            *reinterpret_cast<uint4*>(&xs_hi[r][f4 * 4]) = hb;
            *reinterpret_cast<uint4*>(&xs_lo[r][f4 * 4]) = lb;
        }
        asm volatile("cp.async.wait_group 0;" ::: "memory");
        __syncthreads();

        #pragma unroll
        for (int kst = 0; kst < 4; kst++){
            const int r0 = wid * 16 + grp;
            const int c0 = kst * 8 + qid;
            uint ah0 = xs_hi[r0][c0],   ah1 = xs_hi[r0+8][c0];
            uint ah2 = xs_hi[r0][c0+4], ah3 = xs_hi[r0+8][c0+4];
            uint al0 = xs_lo[r0][c0],   al1 = xs_lo[r0+8][c0];
            uint al2 = xs_lo[r0][c0+4], al3 = xs_lo[r0+8][c0+4];
            #pragma unroll
            for (int nt = 0; nt < 13; nt++){
                uint4 bv = bq[kst][nt * 8 + grp][qid];
                MMA_TF32(acc[nt], ah0, ah1, ah2, ah3, bv.x, bv.y);
                MMA_TF32(acc[nt], al0, al1, al2, al3, bv.x, bv.y);
                MMA_TF32(acc[nt], ah0, ah1, ah2, ah3, bv.z, bv.w);
            }
        }
    }

    const size_t rg = (size_t)(rowbase + wid * 16 + grp);
    #pragma unroll
    for (int nt = 0; nt < 13; nt++){
        int col = nt * 8 + 2 * qid;
        float2 bsv = *reinterpret_cast<const float2*>(&g_bsum[col]);
        float2 v0 = { acc[nt][0] + bsv.x, acc[nt][1] + bsv.y };
        float2 v1 = { acc[nt][2] + bsv.x, acc[nt][3] + bsv.y };
        *reinterpret_cast<float2*>(&g_gates[ rg      * NGP + col]) = v0;
        *reinterpret_cast<float2*>(&g_gates[(rg + 8) * NGP + col]) = v1;
    }
}

// ---------------------------------------------------------------------------
// Kernel 2: LSTM scan with helper-warp FC offload.
// Block = 128 threads: warps 0,1 = scan (batches 2bx, 2bx+1) on SMSP 0,1;
// warps 2,3 = FC helpers for the same batches on SMSP 2,3.
// h flows via a 32-slot smem ring; 16-step epochs, double-buffered halves,
// one __syncthreads per epoch. Helpers compute out[t] = h_t @ W_fc^T + b_fc.
// Scan critical stream drops from 75 to 50 FMA2 per step.
// ---------------------------------------------------------------------------
#define RD   16   // gx ring slots
#define RPD  12   // gx prefetch distance
#define EP   16   // steps per epoch
#define NEP  (NT/EP)   // 64 epochs

__global__ void __launch_bounds__(128, 1) lstm_kernel(
    const float* __restrict__ W_hh, const float* __restrict__ W_fc,
    const float* __restrict__ b_fc, float* __restrict__ out)
{
    __shared__ ull ring[2][RD][32][2];    // gx cp.async ring per scan warp
    __shared__ ull hring[2][2*EP][32];    // duplicated h pairs [batch][slot][lane]

    const int tid  = threadIdx.x;
    const int lane = tid & 31;
    const int wrp  = tid >> 5;            // 0..3
    const int bw   = wrp & 1;             // batch slot within block
    const int b    = blockIdx.x * 2 + bw;
    const bool is_scan = (wrp < 2);

    if (is_scan){
        // ------------------- producer: LSTM recurrence -------------------
        const int k = (lane < NH) ? lane : NH - 1;
        const float* gx = g_gates + (size_t)b * NT * NGP + 4 * k;

        ull w_if[NH], w_go[NH];
        #pragma unroll
        for (int kk = 0; kk < NH; kk++){
            w_if[kk] = pack2(__ldg(W_hh + (     k) * NH + kk), __ldg(W_hh + (NH  + k) * NH + kk));
            w_go[kk] = pack2(__ldg(W_hh + (2*NH+k) * NH + kk), __ldg(W_hh + (3*NH+k) * NH + kk));
        }

        const unsigned rbase = smem_u32(&ring[bw][0][lane][0]);
        #define SLOT_ADDR(s) (rbase + (unsigned)(s) * (32u * 16u))

        #pragma unroll
        for (int d = 0; d < RPD; d++){
            asm volatile("cp.async.ca.shared.global [%0], [%1], 16;"
                         :: "r"(SLOT_ADDR(d)), "l"(gx + (size_t)d * NGP) : "memory");
            asm volatile("cp.async.commit_group;" ::: "memory");
        }

        float h = 0.0f, c = 0.0f;

        for (int e = 0; e <= NEP; e++){
            if (e < NEP){
                #pragma unroll 4
                for (int u = 0; u < EP; u++){
                    const int t = e * EP + u;
                    asm volatile("cp.async.wait_group 11;" ::: "memory");
                    float4 pv = *reinterpret_cast<const float4*>(
                                    &ring[bw][t & (RD-1)][lane][0]);

                    {   // refill slot t+RPD
                        unsigned pred = (t + RPD < NT) ? 1u : 0u;
                        asm volatile(
                            "{ .reg .pred q; setp.ne.u32 q, %0, 0;"
                            "  @q cp.async.ca.shared.global [%1], [%2], 16; }"
                            :: "r"(pred), "r"(SLOT_ADDR((t + RPD) & (RD-1))),
                               "l"(gx + (size_t)(t + RPD) * NGP) : "memory");
                        asm volatile("cp.async.commit_group;" ::: "memory");
                    }

                    ull aif[4], ago[4];
                    aif[0] = pack2(pv.x, pv.y); aif[1] = 0ull; aif[2] = 0ull; aif[3] = 0ull;
                    ago[0] = pack2(pv.z, pv.w); ago[1] = 0ull; ago[2] = 0ull; ago[3] = 0ull;

                    #pragma unroll
                    for (int kk = 0; kk < NH; kk++){
                        float hv = __shfl_sync(0xffffffffu, h, kk);
                        ull hd = pack2(hv, hv);
                        aif[kk & 3] = fma2(hd, w_if[kk], aif[kk & 3]);
                        ago[kk & 3] = fma2(hd, w_go[kk], ago[kk & 3]);
                    }

                    float2 gif = unpack2(add2(add2(aif[0], aif[1]), add2(aif[2], aif[3])));
                    float2 ggo = unpack2(add2(add2(ago[0], ago[1]), add2(ago[2], ago[3])));
                    float iv = sig_t(gif.x);
                    float fv = sig_t(gif.y);
                    float gv = tanha(ggo.x);
                    float ov = sig_t(ggo.y);
                    c = fv * c + iv * gv;
                    h = ov * tanha(c);

                    hring[bw][t & (2*EP - 1)][lane] = pack2(h, h);
                }
            }
            __syncthreads();   // publish epoch e half; helpers drained e-1
        }
        #undef SLOT_ADDR
    } else {
        // ------------------- consumer: FC head -------------------
        const int o0 = 2 * lane;
        float* ob = out + (size_t)b * NT * NO + o0;

        ull wf[NH];
        #pragma unroll
        for (int kk = 0; kk < NH; kk++)
            wf[kk] = pack2(__ldg(W_fc + o0 * NH + kk), __ldg(W_fc + (o0+1) * NH + kk));
        const ull bfc = pack2(__ldg(b_fc + o0), __ldg(b_fc + o0 + 1));

        for (int e = 0; e <= NEP; e++){
            if (e > 0){
                #pragma unroll 4
                for (int u = 0; u < EP; u++){
                    const int t = (e - 1) * EP + u;
                    ull a0 = bfc, a1 = 0ull;
                    #pragma unroll
                    for (int kk = 0; kk < NH; kk++){
                        ull hd = hring[bw][t & (2*EP - 1)][kk];  // LDS.64 bcast
                        if (kk & 1) a1 = fma2(hd, wf[kk], a1);
                        else        a0 = fma2(hd, wf[kk], a0);
                    }
                    *reinterpret_cast<float2*>(ob + (size_t)t * NO) =
                        unpack2(add2(a0, a1));
                }
            }
            __syncthreads();
        }
    }
}

extern "C" void kernel_launch(void* const* d_in, const int* in_sizes, int n_in,
                              void* d_out, int out_size)
{
    (void)in_sizes; (void)n_in; (void)out_size;
    const float* x    = (const float*)d_in[0];
    const float* W_ih = (const float*)d_in[1];
    const float* W_hh = (const float*)d_in[2];
    const float* b_ih = (const float*)d_in[3];
    const float* b_hh = (const float*)d_in[4];
    const float* W_fc = (const float*)d_in[5];
    const float* b_fc = (const float*)d_in[6];
    float* out = (float*)d_out;

    prep_kernel<<<8, 256>>>(W_ih, b_ih, b_hh);
    gates_kernel<<<NM / 64, 128>>>(x);
    lstm_kernel<<<NB / 2, 128>>>(W_hh, W_fc, b_fc, out);
}